// round 4
// baseline (speedup 1.0000x reference)
#include <cuda_runtime.h>
#include <cstdint>

#define N_NODES 100000
#define N_EDGES 1600000
#define DIM 128
#define SCAN_B 1024
#define N_SCAN_BLOCKS ((N_NODES + SCAN_B - 1) / SCAN_B)   // 98

// Static device scratch (allocation rules forbid cudaMalloc).
__device__ float              g_h[(size_t)N_NODES * DIM];   // 51.2 MB
__device__ int                g_cnt[N_NODES];
__device__ int                g_off[N_NODES + 1];
__device__ int                g_cursor[N_NODES];
__device__ unsigned long long g_scan_st[N_SCAN_BLOCKS];     // (flag<<32)|sum; 1=agg, 2=prefix
__device__ uint2              g_edge[N_EDGES];              // (col, val-bits)

// ---------------------------------------------------------------------------
// Packed fp32x2 FMA (SASS FFMA2) — only reachable via PTX.
// ---------------------------------------------------------------------------
__device__ __forceinline__ void ffma2(unsigned long long& d,
                                      unsigned long long a,
                                      unsigned long long b) {
    asm("fma.rn.f32x2 %0, %1, %2, %0;" : "+l"(d) : "l"(a), "l"(b));
}
__device__ __forceinline__ unsigned long long pack2(float lo, float hi) {
    unsigned long long r;
    asm("mov.b64 %0, {%1, %2};" : "=l"(r) : "f"(lo), "f"(hi));
    return r;
}
__device__ __forceinline__ float2 unpack2(unsigned long long v) {
    float2 r;
    asm("mov.b64 {%0, %1}, %2;" : "=f"(r.x), "=f"(r.y) : "l"(v));
    return r;
}

// ---------------------------------------------------------------------------
// Kernel 1: h = x@W + b via FFMA2 (pair over K: lo=even-k partial, hi=odd-k).
// Tile 64 rows x 128 cols per 256-thread block; thread = 8 rows x 4 cols.
// Prologue also zeroes CSR counters + scan state (consumed by later kernels).
// ---------------------------------------------------------------------------
#define TM 64
__global__ __launch_bounds__(256) void gemm_kernel(
    const float* __restrict__ x, const float* __restrict__ W,
    const float* __restrict__ b)
{
    // --- fused CSR-state reset (no sync needed; consumers are later kernels) ---
    {
        int gtid = blockIdx.x * 256 + threadIdx.x;
        if (gtid < N_NODES) g_cnt[gtid] = 0;
        if (gtid < N_SCAN_BLOCKS) g_scan_st[gtid] = 0ull;
        if (gtid == 0) g_off[N_NODES] = N_EDGES;
    }

    __shared__ float Xs[TM][DIM];   // row-major, 32 KB

    const int tid = threadIdx.x;
    const int tx  = tid & 31;           // cols [4tx, 4tx+4)
    const int ty  = tid >> 5;           // rows [8ty, 8ty+8) in tile
    const int block_row = blockIdx.x * TM;

    {
        const float4* xg = reinterpret_cast<const float4*>(x) + (size_t)block_row * (DIM / 4);
        float4* xs4 = reinterpret_cast<float4*>(&Xs[0][0]);
        #pragma unroll
        for (int i = 0; i < 8; i++) {
            int idx = tid + i * 256;
            int row = block_row + (idx >> 5);
            xs4[idx] = (row < N_NODES) ? xg[idx] : make_float4(0.f, 0.f, 0.f, 0.f);
        }
    }
    __syncthreads();

    // acc2[r][c]: f32x2, lo accumulates even-k products, hi odd-k. Init lo with bias.
    unsigned long long acc2[8][4];
    {
        float4 bv = reinterpret_cast<const float4*>(b)[tx];
        #pragma unroll
        for (int r = 0; r < 8; r++) {
            acc2[r][0] = pack2(bv.x, 0.f);
            acc2[r][1] = pack2(bv.y, 0.f);
            acc2[r][2] = pack2(bv.z, 0.f);
            acc2[r][3] = pack2(bv.w, 0.f);
        }
    }

    const float4* W4 = reinterpret_cast<const float4*>(W);
    #pragma unroll 2
    for (int k = 0; k < DIM; k += 2) {
        float4 wa = __ldg(W4 + (k + 0) * (DIM / 4) + tx);   // W[k][4tx..]
        float4 wb = __ldg(W4 + (k + 1) * (DIM / 4) + tx);   // W[k+1][4tx..]
        unsigned long long wp0 = pack2(wa.x, wb.x);
        unsigned long long wp1 = pack2(wa.y, wb.y);
        unsigned long long wp2 = pack2(wa.z, wb.z);
        unsigned long long wp3 = pack2(wa.w, wb.w);
        #pragma unroll
        for (int r = 0; r < 8; r++) {
            // contiguous (x[r][k], x[r][k+1]) — LDS.64 broadcast, 8B-aligned (k even)
            unsigned long long xp =
                *reinterpret_cast<const unsigned long long*>(&Xs[ty * 8 + r][k]);
            ffma2(acc2[r][0], xp, wp0);
            ffma2(acc2[r][1], xp, wp1);
            ffma2(acc2[r][2], xp, wp2);
            ffma2(acc2[r][3], xp, wp3);
        }
    }

    #pragma unroll
    for (int r = 0; r < 8; r++) {
        int row = block_row + ty * 8 + r;
        if (row < N_NODES) {
            float2 a0 = unpack2(acc2[r][0]);
            float2 a1 = unpack2(acc2[r][1]);
            float2 a2 = unpack2(acc2[r][2]);
            float2 a3 = unpack2(acc2[r][3]);
            reinterpret_cast<float4*>(g_h + (size_t)row * DIM)[tx] =
                make_float4(a0.x + a0.y, a1.x + a1.y, a2.x + a2.y, a3.x + a3.y);
        }
    }
}

// ---------------------------------------------------------------------------
// Kernel 2: histogram of rows (counters zeroed by gemm prologue).
// ---------------------------------------------------------------------------
__global__ void hist_kernel(const int* __restrict__ rows) {
    int e = blockIdx.x * blockDim.x + threadIdx.x;
    if (e < N_EDGES) atomicAdd(&g_cnt[rows[e]], 1);
}

// ---------------------------------------------------------------------------
// Kernel 3: single-pass exclusive scan with decoupled lookback.
// 98 blocks x 1024 threads (one wave; lookback waits only on lower bids).
// ---------------------------------------------------------------------------
__global__ __launch_bounds__(SCAN_B) void scan_kernel() {
    __shared__ int s_warp[32];      // warp sums -> exclusive warp offsets
    __shared__ int s_excl;          // block exclusive prefix

    const int b    = blockIdx.x;
    const int lane = threadIdx.x & 31;
    const int wid  = threadIdx.x >> 5;
    const int i    = b * SCAN_B + threadIdx.x;

    int v = (i < N_NODES) ? g_cnt[i] : 0;

    // warp inclusive scan
    int incl = v;
    #pragma unroll
    for (int d = 1; d < 32; d <<= 1) {
        int t = __shfl_up_sync(0xffffffffu, incl, d);
        if (lane >= d) incl += t;
    }
    if (lane == 31) s_warp[wid] = incl;
    __syncthreads();

    if (wid == 0) {
        int ws = s_warp[lane];
        int wincl = ws;
        #pragma unroll
        for (int d = 1; d < 32; d <<= 1) {
            int t = __shfl_up_sync(0xffffffffu, wincl, d);
            if (lane >= d) wincl += t;
        }
        s_warp[lane] = wincl - ws;                       // exclusive warp offset
        int total = __shfl_sync(0xffffffffu, wincl, 31); // block aggregate

        if (lane == 0) {
            if (b == 0) {
                atomicExch(&g_scan_st[0], (2ull << 32) | (unsigned)total);
                s_excl = 0;
            } else {
                atomicExch(&g_scan_st[b], (1ull << 32) | (unsigned)total);
                // lookback
                int run = 0;
                int j = b - 1;
                while (true) {
                    unsigned long long s;
                    do {
                        s = atomicAdd(&g_scan_st[j], 0ull);
                        if ((s >> 32) == 0) __nanosleep(64);
                    } while ((s >> 32) == 0);
                    run += (int)(s & 0xffffffffu);
                    if ((s >> 32) == 2) break;
                    j--;
                }
                s_excl = run;
                atomicExch(&g_scan_st[b], (2ull << 32) | (unsigned)(run + total));
            }
        }
    }
    __syncthreads();

    if (i < N_NODES) {
        int o = s_excl + s_warp[wid] + (incl - v);   // global exclusive prefix
        g_off[i]    = o;
        g_cursor[i] = o;
    }
}

// ---------------------------------------------------------------------------
// Kernel 4: fill packed edge list (col, val) per destination node.
// ---------------------------------------------------------------------------
__global__ void fill_kernel(const int* __restrict__ rows,
                            const int* __restrict__ cols,
                            const float* __restrict__ vals) {
    int e = blockIdx.x * blockDim.x + threadIdx.x;
    if (e < N_EDGES) {
        int pos = atomicAdd(&g_cursor[rows[e]], 1);
        g_edge[pos] = make_uint2((unsigned)cols[e], __float_as_uint(vals[e]));
    }
}

// ---------------------------------------------------------------------------
// Kernel 5: pull-gather. One warp per node; lane = one float4 of the row.
// ---------------------------------------------------------------------------
__global__ __launch_bounds__(256) void gather_kernel(float* __restrict__ out) {
    const int node = (blockIdx.x * 256 + threadIdx.x) >> 5;
    if (node >= N_NODES) return;
    const int lane = threadIdx.x & 31;

    const int beg = __ldg(&g_off[node]);
    const int end = __ldg(&g_off[node + 1]);

    const float4* h4 = reinterpret_cast<const float4*>(g_h);
    float4 acc = make_float4(0.f, 0.f, 0.f, 0.f);

    int i = beg;
    for (; i + 1 < end; i += 2) {
        uint2 e0 = __ldg(&g_edge[i]);
        uint2 e1 = __ldg(&g_edge[i + 1]);
        float4 a0 = __ldg(h4 + (size_t)e0.x * 32 + lane);
        float4 a1 = __ldg(h4 + (size_t)e1.x * 32 + lane);
        float v0 = __uint_as_float(e0.y);
        float v1 = __uint_as_float(e1.y);
        acc.x += v0 * a0.x; acc.y += v0 * a0.y;
        acc.z += v0 * a0.z; acc.w += v0 * a0.w;
        acc.x += v1 * a1.x; acc.y += v1 * a1.y;
        acc.z += v1 * a1.z; acc.w += v1 * a1.w;
    }
    if (i < end) {
        uint2 e0 = __ldg(&g_edge[i]);
        float4 a0 = __ldg(h4 + (size_t)e0.x * 32 + lane);
        float v0 = __uint_as_float(e0.y);
        acc.x += v0 * a0.x; acc.y += v0 * a0.y;
        acc.z += v0 * a0.z; acc.w += v0 * a0.w;
    }

    reinterpret_cast<float4*>(out)[(size_t)node * 32 + lane] = acc;
}

// ---------------------------------------------------------------------------
extern "C" void kernel_launch(void* const* d_in, const int* in_sizes, int n_in,
                              void* d_out, int out_size)
{
    const float* x    = (const float*)d_in[0];
    const float* W    = (const float*)d_in[1];
    const float* b    = (const float*)d_in[2];
    const float* vals = (const float*)d_in[3];
    const int*   rows = (const int*)d_in[4];
    const int*   cols = (const int*)d_in[5];
    float* out = (float*)d_out;

    const int EB = (N_EDGES + 255) / 256;

    // 1. GEMM (also resets CSR counters / scan state / sentinel)
    gemm_kernel<<<(N_NODES + TM - 1) / TM, 256>>>(x, W, b);
    // 2. in-degree histogram
    hist_kernel<<<EB, 256>>>(rows);
    // 3. single-pass exclusive scan (decoupled lookback)
    scan_kernel<<<N_SCAN_BLOCKS, SCAN_B>>>();
    // 4. CSR edge fill
    fill_kernel<<<EB, 256>>>(rows, cols, vals);
    // 5. pull-gather
    gather_kernel<<<(N_NODES * 32 + 255) / 256, 256>>>(out);
}

// round 5
// speedup vs baseline: 1.0643x; 1.0643x over previous
#include <cuda_runtime.h>
#include <cstdint>

#define N_NODES 100000
#define N_EDGES 1600000
#define DIM 128
#define SCAN_B 1024
#define N_SCAN_BLOCKS ((N_NODES + SCAN_B - 1) / SCAN_B)   // 98

// Static device scratch (zero-initialized at module load; gather re-zeroes
// g_cnt / g_scan_st at the start of each call for the next replay).
__device__ float              g_h[(size_t)N_NODES * DIM];   // 51.2 MB
__device__ int                g_cnt[N_NODES];
__device__ int                g_off[N_NODES + 1];
__device__ int                g_cursor[N_NODES];
__device__ unsigned long long g_scan_st[N_SCAN_BLOCKS];     // (flag<<32)|sum; 1=agg, 2=prefix
__device__ uint2              g_edge[N_EDGES];              // (col, val-bits)

// ---------------------------------------------------------------------------
// Packed fp32x2 FMA (SASS FFMA2) — only reachable via PTX.
// ---------------------------------------------------------------------------
__device__ __forceinline__ void ffma2(unsigned long long& d,
                                      unsigned long long a,
                                      unsigned long long b) {
    asm("fma.rn.f32x2 %0, %1, %2, %0;" : "+l"(d) : "l"(a), "l"(b));
}
__device__ __forceinline__ unsigned long long pack2(float lo, float hi) {
    unsigned long long r;
    asm("mov.b64 %0, {%1, %2};" : "=l"(r) : "f"(lo), "f"(hi));
    return r;
}
__device__ __forceinline__ float2 unpack2(unsigned long long v) {
    float2 r;
    asm("mov.b64 {%0, %1}, %2;" : "=f"(r.x), "=f"(r.y) : "l"(v));
    return r;
}

// ---------------------------------------------------------------------------
// Kernel 1: h = x@W + b via FFMA2 (pair over K), with the in-degree histogram
// fused into the prologue (no-return RED.ADDs overlap the FFMA mainloop).
// Counters were zeroed by the previous call's gather (or module load).
// ---------------------------------------------------------------------------
#define TM 64
__global__ __launch_bounds__(256) void gemm_kernel(
    const float* __restrict__ x, const float* __restrict__ W,
    const float* __restrict__ b, const int* __restrict__ rows)
{
    // --- fused histogram: 4 edges per thread, coalesced int4 load ---
    {
        int t = blockIdx.x * 256 + threadIdx.x;
        if (t < N_EDGES / 4) {
            int4 r4 = __ldg(reinterpret_cast<const int4*>(rows) + t);
            atomicAdd(&g_cnt[r4.x], 1);   // no-return -> RED.ADD
            atomicAdd(&g_cnt[r4.y], 1);
            atomicAdd(&g_cnt[r4.z], 1);
            atomicAdd(&g_cnt[r4.w], 1);
        }
    }

    __shared__ float Xs[TM][DIM];   // row-major, 32 KB

    const int tid = threadIdx.x;
    const int tx  = tid & 31;           // cols [4tx, 4tx+4)
    const int ty  = tid >> 5;           // rows [8ty, 8ty+8) in tile
    const int block_row = blockIdx.x * TM;

    {
        const float4* xg = reinterpret_cast<const float4*>(x) + (size_t)block_row * (DIM / 4);
        float4* xs4 = reinterpret_cast<float4*>(&Xs[0][0]);
        #pragma unroll
        for (int i = 0; i < 8; i++) {
            int idx = tid + i * 256;
            int row = block_row + (idx >> 5);
            xs4[idx] = (row < N_NODES) ? xg[idx] : make_float4(0.f, 0.f, 0.f, 0.f);
        }
    }
    __syncthreads();

    // acc2[r][c]: f32x2, lo accumulates even-k products, hi odd-k. Init lo with bias.
    unsigned long long acc2[8][4];
    {
        float4 bv = reinterpret_cast<const float4*>(b)[tx];
        #pragma unroll
        for (int r = 0; r < 8; r++) {
            acc2[r][0] = pack2(bv.x, 0.f);
            acc2[r][1] = pack2(bv.y, 0.f);
            acc2[r][2] = pack2(bv.z, 0.f);
            acc2[r][3] = pack2(bv.w, 0.f);
        }
    }

    const float4* W4 = reinterpret_cast<const float4*>(W);
    #pragma unroll 2
    for (int k = 0; k < DIM; k += 2) {
        float4 wa = __ldg(W4 + (k + 0) * (DIM / 4) + tx);
        float4 wb = __ldg(W4 + (k + 1) * (DIM / 4) + tx);
        unsigned long long wp0 = pack2(wa.x, wb.x);
        unsigned long long wp1 = pack2(wa.y, wb.y);
        unsigned long long wp2 = pack2(wa.z, wb.z);
        unsigned long long wp3 = pack2(wa.w, wb.w);
        #pragma unroll
        for (int r = 0; r < 8; r++) {
            unsigned long long xp =
                *reinterpret_cast<const unsigned long long*>(&Xs[ty * 8 + r][k]);
            ffma2(acc2[r][0], xp, wp0);
            ffma2(acc2[r][1], xp, wp1);
            ffma2(acc2[r][2], xp, wp2);
            ffma2(acc2[r][3], xp, wp3);
        }
    }

    #pragma unroll
    for (int r = 0; r < 8; r++) {
        int row = block_row + ty * 8 + r;
        if (row < N_NODES) {
            float2 a0 = unpack2(acc2[r][0]);
            float2 a1 = unpack2(acc2[r][1]);
            float2 a2 = unpack2(acc2[r][2]);
            float2 a3 = unpack2(acc2[r][3]);
            reinterpret_cast<float4*>(g_h + (size_t)row * DIM)[tx] =
                make_float4(a0.x + a0.y, a1.x + a1.y, a2.x + a2.y, a3.x + a3.y);
        }
    }
}

// ---------------------------------------------------------------------------
// Kernel 2: single-pass exclusive scan, WARP-PARALLEL decoupled lookback.
// Lane l polls state[b-1-l]; ballot for nearest prefix; slide window by 32.
// ---------------------------------------------------------------------------
__global__ __launch_bounds__(SCAN_B) void scan_kernel() {
    __shared__ int s_warp[32];
    __shared__ int s_excl;

    const int b    = blockIdx.x;
    const int lane = threadIdx.x & 31;
    const int wid  = threadIdx.x >> 5;
    const int i    = b * SCAN_B + threadIdx.x;

    if (i == 0) g_off[N_NODES] = N_EDGES;

    int v = (i < N_NODES) ? g_cnt[i] : 0;

    // warp inclusive scan
    int incl = v;
    #pragma unroll
    for (int d = 1; d < 32; d <<= 1) {
        int t = __shfl_up_sync(0xffffffffu, incl, d);
        if (lane >= d) incl += t;
    }
    if (lane == 31) s_warp[wid] = incl;
    __syncthreads();

    if (wid == 0) {
        int ws = s_warp[lane];
        int wincl = ws;
        #pragma unroll
        for (int d = 1; d < 32; d <<= 1) {
            int t = __shfl_up_sync(0xffffffffu, wincl, d);
            if (lane >= d) wincl += t;
        }
        s_warp[lane] = wincl - ws;                       // exclusive warp offset
        int total = __shfl_sync(0xffffffffu, wincl, 31); // block aggregate

        // publish aggregate (block 0 publishes its prefix directly)
        if (lane == 0)
            atomicExch(&g_scan_st[b],
                       ((b == 0 ? 2ull : 1ull) << 32) | (unsigned)total);

        int excl = 0;
        if (b > 0) {
            int base = b;
            while (true) {
                int j = base - 1 - lane;                 // lane 0 = nearest
                int flag;
                unsigned agg = 0;
                if (j >= 0) {
                    unsigned long long s;
                    do {
                        s = atomicAdd(&g_scan_st[j], 0ull);
                        flag = (int)(s >> 32);
                        if (!flag) __nanosleep(32);
                    } while (!flag);
                    agg = (unsigned)s;
                } else {
                    flag = 2;                            // virtual prefix 0
                }
                unsigned ball = __ballot_sync(0xffffffffu, flag == 2);
                int val = (int)agg;
                if (ball) {
                    int first = __ffs(ball) - 1;         // nearest prefix lane
                    if (lane > first) val = 0;           // drop beyond prefix
                }
                #pragma unroll
                for (int d = 16; d; d >>= 1)
                    val += __shfl_xor_sync(0xffffffffu, val, d);
                excl += val;
                if (ball) break;
                base -= 32;
            }
            if (lane == 0)
                atomicExch(&g_scan_st[b], (2ull << 32) | (unsigned)(excl + total));
        }
        if (lane == 0) s_excl = excl;
    }
    __syncthreads();

    if (i < N_NODES) {
        int o = s_excl + s_warp[wid] + (incl - v);
        g_off[i]    = o;
        g_cursor[i] = o;
    }
}

// ---------------------------------------------------------------------------
// Kernel 3: fill packed edge list (col, val) per destination node.
// ---------------------------------------------------------------------------
__global__ void fill_kernel(const int* __restrict__ rows,
                            const int* __restrict__ cols,
                            const float* __restrict__ vals) {
    int e = blockIdx.x * blockDim.x + threadIdx.x;
    if (e < N_EDGES) {
        int pos = atomicAdd(&g_cursor[rows[e]], 1);
        g_edge[pos] = make_uint2((unsigned)cols[e], __float_as_uint(vals[e]));
    }
}

// ---------------------------------------------------------------------------
// Kernel 4: pull-gather. One warp per node; lane = one float4 of the row.
// Prologue re-zeroes g_cnt / g_scan_st for the NEXT call (this call's scan
// and fill already consumed them).
// ---------------------------------------------------------------------------
__global__ __launch_bounds__(256) void gather_kernel(float* __restrict__ out) {
    {
        int gt = blockIdx.x * 256 + threadIdx.x;   // up to 3.2M threads
        if (gt < N_NODES) g_cnt[gt] = 0;
        if (gt < N_SCAN_BLOCKS) g_scan_st[gt] = 0ull;
    }

    const int node = (blockIdx.x * 256 + threadIdx.x) >> 5;
    if (node >= N_NODES) return;
    const int lane = threadIdx.x & 31;

    const int beg = __ldg(&g_off[node]);
    const int end = __ldg(&g_off[node + 1]);

    const float4* h4 = reinterpret_cast<const float4*>(g_h);
    float4 acc = make_float4(0.f, 0.f, 0.f, 0.f);

    int i = beg;
    for (; i + 1 < end; i += 2) {
        uint2 e0 = __ldg(&g_edge[i]);
        uint2 e1 = __ldg(&g_edge[i + 1]);
        float4 a0 = __ldg(h4 + (size_t)e0.x * 32 + lane);
        float4 a1 = __ldg(h4 + (size_t)e1.x * 32 + lane);
        float v0 = __uint_as_float(e0.y);
        float v1 = __uint_as_float(e1.y);
        acc.x += v0 * a0.x; acc.y += v0 * a0.y;
        acc.z += v0 * a0.z; acc.w += v0 * a0.w;
        acc.x += v1 * a1.x; acc.y += v1 * a1.y;
        acc.z += v1 * a1.z; acc.w += v1 * a1.w;
    }
    if (i < end) {
        uint2 e0 = __ldg(&g_edge[i]);
        float4 a0 = __ldg(h4 + (size_t)e0.x * 32 + lane);
        float v0 = __uint_as_float(e0.y);
        acc.x += v0 * a0.x; acc.y += v0 * a0.y;
        acc.z += v0 * a0.z; acc.w += v0 * a0.w;
    }

    reinterpret_cast<float4*>(out)[(size_t)node * 32 + lane] = acc;
}

// ---------------------------------------------------------------------------
extern "C" void kernel_launch(void* const* d_in, const int* in_sizes, int n_in,
                              void* d_out, int out_size)
{
    const float* x    = (const float*)d_in[0];
    const float* W    = (const float*)d_in[1];
    const float* b    = (const float*)d_in[2];
    const float* vals = (const float*)d_in[3];
    const int*   rows = (const int*)d_in[4];
    const int*   cols = (const int*)d_in[5];
    float* out = (float*)d_out;

    const int EB = (N_EDGES + 255) / 256;

    // 1. GEMM + fused in-degree histogram
    gemm_kernel<<<(N_NODES + TM - 1) / TM, 256>>>(x, W, b, rows);
    // 2. single-pass exclusive scan (warp-parallel lookback)
    scan_kernel<<<N_SCAN_BLOCKS, SCAN_B>>>();
    // 3. CSR edge fill
    fill_kernel<<<EB, 256>>>(rows, cols, vals);
    // 4. pull-gather (+ state reset for next replay)
    gather_kernel<<<(N_NODES * 32 + 255) / 256, 256>>>(out);
}